// round 1
// baseline (speedup 1.0000x reference)
#include <cuda_runtime.h>

#define GD 256
#define GH 256
#define GW 256
#define RWIN 6
static const long long DHW = (long long)GD * GH * GW;

// ---------------------------------------------------------------------------
// Zero-init the two output volumes (2 * 256^3 fp32 = 128MB), vectorized.
// ---------------------------------------------------------------------------
__global__ void zero_kernel(float4* __restrict__ out, int n4) {
    int i = blockIdx.x * blockDim.x + threadIdx.x;
    int stride = gridDim.x * blockDim.x;
    float4 z = make_float4(0.f, 0.f, 0.f, 0.f);
    for (; i < n4; i += stride) out[i] = z;
}

// ---------------------------------------------------------------------------
// One CTA per Gaussian. Crop the 13^3 window to the integer bbox
// [floor(c-r), ceil(c+r)] ∩ [0,255] ∩ [base-6, base+6]  (exactly equivalent
// to the reference's in_bbox & in_grid masks since the bbox bounds are
// integer-valued floats). Threads grid-stride over the cropped box,
// evaluate the Mahalanobis form, and scatter with global fp32 REDs.
// ---------------------------------------------------------------------------
__global__ __launch_bounds__(256)
void splat_kernel(const float* __restrict__ center,
                  const float* __restrict__ covinv,
                  const float* __restrict__ dens_r,
                  const float* __restrict__ dens_i,
                  const float* __restrict__ radius,
                  const float* __restrict__ half_shape,
                  float* __restrict__ out, int N)
{
    int g = blockIdx.x;
    if (g >= N) return;

    const float cx = center[3 * g + 0];
    const float cy = center[3 * g + 1];
    const float cz = center[3 * g + 2];

    const float C00 = covinv[9 * g + 0];
    const float C01 = covinv[9 * g + 1];
    const float C02 = covinv[9 * g + 2];
    const float C10 = covinv[9 * g + 3];
    const float C11 = covinv[9 * g + 4];
    const float C12 = covinv[9 * g + 5];
    const float C20 = covinv[9 * g + 6];
    const float C21 = covinv[9 * g + 7];
    const float C22 = covinv[9 * g + 8];
    // fold symmetric cross terms
    const float S01 = C01 + C10;
    const float S02 = C02 + C20;
    const float S12 = C12 + C21;

    const float r  = radius[g];
    const float wr = dens_r[g];
    const float wi = dens_i[g];

    const float ihx = 1.0f / half_shape[0];
    const float ihy = 1.0f / half_shape[1];
    const float ihz = 1.0f / half_shape[2];

    const int bx = (int)floorf(cx);
    const int by = (int)floorf(cy);
    const int bz = (int)floorf(cz);

    // integer bbox (floor/ceil give integer-valued floats; int cast is exact)
    int lox = (int)floorf(cx - r) - bx;  int hix = (int)ceilf(cx + r) - bx;
    int loy = (int)floorf(cy - r) - by;  int hiy = (int)ceilf(cy + r) - by;
    int loz = (int)floorf(cz - r) - bz;  int hiz = (int)ceilf(cz + r) - bz;

    // clamp to the reference's fixed +/-6 window and to the grid
    lox = max(lox, max(-RWIN, -bx));          hix = min(hix, min(RWIN, GD - 1 - bx));
    loy = max(loy, max(-RWIN, -by));          hiy = min(hiy, min(RWIN, GH - 1 - by));
    loz = max(loz, max(-RWIN, -bz));          hiz = min(hiz, min(RWIN, GW - 1 - bz));

    const int nx = hix - lox + 1;
    const int ny = hiy - loy + 1;
    const int nz = hiz - loz + 1;
    if (nx <= 0 || ny <= 0 || nz <= 0) return;

    const int total = nx * ny * nz;

    float* __restrict__ out_r = out;
    float* __restrict__ out_i = out + DHW;

    for (int k = threadIdx.x; k < total; k += blockDim.x) {
        int oz = k % nz;
        int t  = k / nz;
        int oy = t % ny;
        int ox = t / ny;

        const int vx = bx + lox + ox;
        const int vy = by + loy + oy;
        const int vz = bz + loz + oz;

        const float dx = ((float)vx - cx) * ihx;
        const float dy = ((float)vy - cy) * ihy;
        const float dz = ((float)vz - cz) * ihz;

        // Md = d^T C d with symmetric fold
        float Md = C00 * dx * dx;
        Md = fmaf(C11 * dy, dy, Md);
        Md = fmaf(C22 * dz, dz, Md);
        Md = fmaf(S01 * dx, dy, Md);
        Md = fmaf(S02 * dx, dz, Md);
        Md = fmaf(S12 * dy, dz, Md);

        if (Md <= 9.0f) {
            const float w = __expf(-0.5f * Md);
            const int idx = (vx * GH + vy) * GW + vz;
            atomicAdd(out_r + idx, w * wr);
            atomicAdd(out_i + idx, w * wi);
        }
    }
}

extern "C" void kernel_launch(void* const* d_in, const int* in_sizes, int n_in,
                              void* d_out, int out_size) {
    const float* center     = (const float*)d_in[0];  // [N,3]
    const float* covinv     = (const float*)d_in[1];  // [N,3,3]
    const float* dens_r     = (const float*)d_in[2];  // [N]
    const float* dens_i     = (const float*)d_in[3];  // [N]
    const float* radius     = (const float*)d_in[4];  // [N]
    const float* half_shape = (const float*)d_in[5];  // [3]

    float* out = (float*)d_out;                       // [2, D, H, W]
    const int N = in_sizes[2];                        // density_r element count

    // zero both volumes
    const int n4 = (int)((2 * DHW) / 4);
    zero_kernel<<<2048, 256>>>((float4*)out, n4);

    // one block per Gaussian
    splat_kernel<<<N, 256>>>(center, covinv, dens_r, dens_i, radius,
                             half_shape, out, N);
}